// round 17
// baseline (speedup 1.0000x reference)
#include <cuda_runtime.h>
#include <cuda_fp16.h>
#include <cstdint>

#define HASH_SIZE 10240
#define PROJ_DIM  128
#define MODEL_DIM 512
#define NBATCH    8
#define SEQ       8192

// Fused table in fp16: fused[h][m] = scale * sum_k E[h][k]*P[m][k]  (10.5 MB)
__device__ __align__(16) unsigned char g_fused_h[HASH_SIZE * MODEL_DIM * 2];

__device__ __forceinline__ uint32_t smem_u32(const void* p) {
    uint32_t a;
    asm("{ .reg .u64 t; cvta.to.shared.u64 t, %1; cvt.u32.u64 %0, t; }" : "=r"(a) : "l"(p));
    return a;
}
__device__ __forceinline__ void ldsm_x4(uint32_t& r0, uint32_t& r1,
                                        uint32_t& r2, uint32_t& r3, uint32_t addr) {
    asm volatile("ldmatrix.sync.aligned.m8n8.x4.shared.b16 {%0,%1,%2,%3}, [%4];"
                 : "=r"(r0), "=r"(r1), "=r"(r2), "=r"(r3) : "r"(addr));
}
__device__ __forceinline__ void mma_f16(float* d, const uint32_t* a, const uint32_t* b) {
    asm volatile("mma.sync.aligned.m16n8k16.row.col.f32.f16.f16.f32 "
                 "{%0,%1,%2,%3}, {%4,%5,%6,%7}, {%8,%9}, {%0,%1,%2,%3};"
                 : "+f"(d[0]), "+f"(d[1]), "+f"(d[2]), "+f"(d[3])
                 : "r"(a[0]), "r"(a[1]), "r"(a[2]), "r"(a[3]), "r"(b[0]), "r"(b[1]));
}
__device__ __forceinline__ uint32_t sw(int row, int chunk) {
    return (uint32_t)(row * 256 + ((chunk ^ (row & 7)) << 4));
}
__device__ __forceinline__ uint4 cvt8_f16(float4 a, float4 b) {
    __half2 h0 = __floats2half2_rn(a.x, a.y);
    __half2 h1 = __floats2half2_rn(a.z, a.w);
    __half2 h2 = __floats2half2_rn(b.x, b.y);
    __half2 h3 = __floats2half2_rn(b.z, b.w);
    return make_uint4(*(uint32_t*)&h0, *(uint32_t*)&h1,
                      *(uint32_t*)&h2, *(uint32_t*)&h3);
}

// ===========================================================================
// Kernel 1: one-tile-per-CTA fp16 GEMM (M=128,N=128,K=128), fused convert.
// 320 CTAs at 2/SM -> 1.08 waves. Epilogue: stage fp16 D tile in padded smem
// (272B row stride: 16B-chunk aligned, banks spread), then stream full lines.
// ===========================================================================
#define A_OFF 0
#define B_OFF 32768
#define D_OFF 65536
#define D_RSTRIDE 272                       // bytes per staged row (17 x 16B)
#define SMEM_DYN (65536 + 128 * D_RSTRIDE + 1024)

__global__ __launch_bounds__(256, 2) void build_table_kernel(
    const float* __restrict__ E,
    const float* __restrict__ P,
    const float* __restrict__ scale_p)
{
    extern __shared__ char smem_raw[];
    const uint32_t sb0   = smem_u32(smem_raw);
    const uint32_t pad   = ((sb0 + 1023) & ~1023u) - sb0;
    char* smp            = smem_raw + pad;
    const uint32_t sbase = sb0 + pad;

    const int tid = threadIdx.x;
    const int m0  = blockIdx.x * 128;
    const int n0  = blockIdx.y * 128;

    // ---- copy+convert A and B (2048 chunks each, 8/thread)
    #pragma unroll
    for (int i = 0; i < 8; i++) {
        const int idx = i * 256 + tid;
        const int row = idx >> 4, chunk = idx & 15;
        const float4* g = (const float4*)(E + (size_t)(m0 + row) * PROJ_DIM + chunk * 8);
        *(uint4*)(smp + A_OFF + sw(row, chunk)) = cvt8_f16(__ldg(g), __ldg(g + 1));
    }
    #pragma unroll
    for (int i = 0; i < 8; i++) {
        const int idx = i * 256 + tid;
        const int row = idx >> 4, chunk = idx & 15;
        const float4* g = (const float4*)(P + (size_t)(n0 + row) * PROJ_DIM + chunk * 8);
        *(uint4*)(smp + B_OFF + sw(row, chunk)) = cvt8_f16(__ldg(g), __ldg(g + 1));
    }
    __syncthreads();

    // ---- mma: warp w -> rows wm*32..+31, cols wn*64..+63
    const int w    = tid >> 5;
    const int lane = tid & 31;
    const int wm   = w & 3;
    const int wn   = w >> 2;

    float acc[2][8][4];
    #pragma unroll
    for (int mf = 0; mf < 2; mf++)
        #pragma unroll
        for (int nf = 0; nf < 8; nf++)
            #pragma unroll
            for (int q = 0; q < 4; q++) acc[mf][nf][q] = 0.0f;

    int rowA[2], rowB[4];
    #pragma unroll
    for (int mf = 0; mf < 2; mf++)
        rowA[mf] = wm * 32 + mf * 16 + (lane & 7) + (lane & 8);
    #pragma unroll
    for (int bp = 0; bp < 4; bp++)
        rowB[bp] = wn * 64 + bp * 16 + (lane & 7) + ((lane & 16) >> 1);
    const int ckA = lane >> 4;
    const int ckB = (lane >> 3) & 1;

    #pragma unroll
    for (int kk = 0; kk < 8; kk++) {
        uint32_t ah[2][4];
        #pragma unroll
        for (int mf = 0; mf < 2; mf++) {
            const uint32_t off = sw(rowA[mf], 2 * kk + ckA);
            ldsm_x4(ah[mf][0], ah[mf][1], ah[mf][2], ah[mf][3], sbase + A_OFF + off);
        }
        uint32_t bh[8][2];
        #pragma unroll
        for (int bp = 0; bp < 4; bp++) {
            const uint32_t off = sw(rowB[bp], 2 * kk + ckB);
            ldsm_x4(bh[2 * bp][0], bh[2 * bp][1], bh[2 * bp + 1][0], bh[2 * bp + 1][1],
                    sbase + B_OFF + off);
        }
        #pragma unroll
        for (int mf = 0; mf < 2; mf++)
            #pragma unroll
            for (int nf = 0; nf < 8; nf++)
                mma_f16(acc[mf][nf], ah[mf], bh[nf]);
    }

    // ---- stage fp16 D tile (scaled) in padded smem
    const float s = __ldg(scale_p);
    #pragma unroll
    for (int mf = 0; mf < 2; mf++) {
        const int r0 = wm * 32 + mf * 16 + (lane >> 2);
        #pragma unroll
        for (int nf = 0; nf < 8; nf++) {
            const int c = wn * 64 + nf * 8 + (lane & 3) * 2;
            __half2 h0 = __floats2half2_rn(acc[mf][nf][0] * s, acc[mf][nf][1] * s);
            __half2 h1 = __floats2half2_rn(acc[mf][nf][2] * s, acc[mf][nf][3] * s);
            *(__half2*)(smp + D_OFF + r0 * D_RSTRIDE + c * 2)       = h0;
            *(__half2*)(smp + D_OFF + (r0 + 8) * D_RSTRIDE + c * 2) = h1;
        }
    }
    __syncthreads();

    // ---- copy-out: 128 rows x 256B = 2048 full 16B lines, 8/thread
    #pragma unroll
    for (int i = 0; i < 8; i++) {
        const int idx = i * 256 + tid;
        const int row = idx >> 4, chunk = idx & 15;
        uint4 v = *(const uint4*)(smp + D_OFF + row * D_RSTRIDE + chunk * 16);
        *(uint4*)(g_fused_h + ((size_t)(m0 + row) * MODEL_DIM + n0) * 2 + chunk * 16) = v;
    }
}

// ===========================================================================
// Kernel 2: hash + gather(fp16 table) + fp32 stream out.
// LTS traffic: 67 MB reads + 134 MB writes (was 268 MB).
// ===========================================================================
__device__ __forceinline__ int hash_at(const int* __restrict__ tok, int t) {
    const int s = t & (SEQ - 1);
    if (s == 0) return HASH_SIZE - 1;
    const int t1 = __ldg(tok + t);
    const int t0 = __ldg(tok + t - 1);
    // products < 2^31: no wrap; matches jnp.mod exactly
    return ((36313 * t1) ^ (27191 * t0)) % (HASH_SIZE - 1);
}

__device__ __forceinline__ void h8_to_f8(uint4 v, float4& lo, float4& hi) {
    float2 f0 = __half22float2(*(__half2*)&v.x);
    float2 f1 = __half22float2(*(__half2*)&v.y);
    float2 f2 = __half22float2(*(__half2*)&v.z);
    float2 f3 = __half22float2(*(__half2*)&v.w);
    lo = make_float4(f0.x, f0.y, f1.x, f1.y);
    hi = make_float4(f2.x, f2.y, f3.x, f3.y);
}

__global__ __launch_bounds__(256) void gather_kernel(
    const int* __restrict__ tok,
    float* __restrict__ out)
{
    const int warp = (blockIdx.x * 256 + threadIdx.x) >> 5;
    const int lane = threadIdx.x & 31;
    const int tA = warp * 2, tB = warp * 2 + 1;

    const int hA = hash_at(tok, tA);
    const int hB = hash_at(tok, tB);

    const uint4* sA = (const uint4*)(g_fused_h + (size_t)hA * MODEL_DIM * 2);
    const uint4* sB = (const uint4*)(g_fused_h + (size_t)hB * MODEL_DIM * 2);
    float4* dA = (float4*)(out + (size_t)tA * MODEL_DIM);
    float4* dB = (float4*)(out + (size_t)tB * MODEL_DIM);

    // 2 fp16 lines per token per lane (64 B -> 64 fp32 B out x2)
    uint4 a0 = __ldg(sA + lane);
    uint4 a1 = __ldg(sA + lane + 32);
    uint4 b0 = __ldg(sB + lane);
    uint4 b1 = __ldg(sB + lane + 32);

    float4 lo, hi;
    h8_to_f8(a0, lo, hi);
    __stcs(dA + lane * 2,      lo);
    __stcs(dA + lane * 2 + 1,  hi);
    h8_to_f8(a1, lo, hi);
    __stcs(dA + 64 + lane * 2,     lo);
    __stcs(dA + 64 + lane * 2 + 1, hi);
    h8_to_f8(b0, lo, hi);
    __stcs(dB + lane * 2,      lo);
    __stcs(dB + lane * 2 + 1,  hi);
    h8_to_f8(b1, lo, hi);
    __stcs(dB + 64 + lane * 2,     lo);
    __stcs(dB + 64 + lane * 2 + 1, hi);
}

// ===========================================================================
// Inputs (metadata order): token_ids(i32), embed_weight(f32), proj_weight(f32), scale(f32[1])
// ===========================================================================
extern "C" void kernel_launch(void* const* d_in, const int* in_sizes, int n_in,
                              void* d_out, int out_size)
{
    const int*   tok   = (const int*)d_in[0];
    const float* E     = (const float*)d_in[1];
    const float* P     = (const float*)d_in[2];
    const float* scale = (const float*)d_in[3];
    float*       out   = (float*)d_out;

    cudaFuncSetAttribute(build_table_kernel,
                         cudaFuncAttributeMaxDynamicSharedMemorySize, SMEM_DYN);

    dim3 gemm_grid(HASH_SIZE / 128, MODEL_DIM / 128);   // (80, 4) = 320 CTAs
    build_table_kernel<<<gemm_grid, 256, SMEM_DYN>>>(E, P, scale);

    gather_kernel<<<(NBATCH * SEQ) / 16, 256>>>(tok, out);
}